// round 6
// baseline (speedup 1.0000x reference)
#include <cuda_runtime.h>

#define G     8
#define CIN   64
#define COUT  64
#define KS    7
#define PAD   3
#define H     56
#define W     56
#define B     4

#define TH    8             // output rows per attn tile
#define TRW   (TH + KS - 1) // 14 staged rows
#define SP    66            // shared row stride (floats), even + bank stagger

// scratch (allocation-free rule), interior 56x56 layout
__device__ float g_q[B*COUT*H*W];
__device__ float g_k[B*COUT*H*W];
__device__ float g_v[B*COUT*H*W];

#define EX2F(dst, src) asm("ex2.approx.ftz.f32 %0, %1;" : "=f"(dst) : "f"(src))

// ---------------------------------------------------------------------------
// Kernel 1: fused grouped 1x1 conv, 4 outputs/thread (float4).
// log2(e) folded into wq.
// ---------------------------------------------------------------------------
__global__ __launch_bounds__(256)
void qkv_kernel(const float* __restrict__ x,
                const float* __restrict__ wq,
                const float* __restrict__ wk,
                const float* __restrict__ bk,
                const float* __restrict__ wv,
                const float* __restrict__ bv) {
    const float LOG2E = 1.4426950408889634f;
    int idx = blockIdx.x * 256 + threadIdx.x;          // 200,704 threads exact
    int t = idx / 14;
    int j = idx - t*14;
    int h = t % 56;  t /= 56;
    int c = t % 64;
    int b = t / 64;
    int g = c >> 3;

    const float4* xp = (const float4*)x + ((b*CIN + g*8)*H + h)*14 + j;

    float kb = __ldg(&bk[c]);
    float vb = __ldg(&bv[c]);
    float4 aq = make_float4(0.f, 0.f, 0.f, 0.f);
    float4 ak = make_float4(kb, kb, kb, kb);
    float4 av = make_float4(vb, vb, vb, vb);

    #pragma unroll
    for (int i = 0; i < 8; i++) {
        float4 xv  = __ldg(xp + i*784);                 // 784 = H*W/4
        float wqi  = __ldg(&wq[c*8 + i]) * LOG2E;
        float wki  = __ldg(&wk[c*8 + i]);
        float wvi  = __ldg(&wv[c*8 + i]);
        aq.x = fmaf(wqi, xv.x, aq.x); aq.y = fmaf(wqi, xv.y, aq.y);
        aq.z = fmaf(wqi, xv.z, aq.z); aq.w = fmaf(wqi, xv.w, aq.w);
        ak.x = fmaf(wki, xv.x, ak.x); ak.y = fmaf(wki, xv.y, ak.y);
        ak.z = fmaf(wki, xv.z, ak.z); ak.w = fmaf(wki, xv.w, ak.w);
        av.x = fmaf(wvi, xv.x, av.x); av.y = fmaf(wvi, xv.y, av.y);
        av.z = fmaf(wvi, xv.z, av.z); av.w = fmaf(wvi, xv.w, av.w);
    }
    ((float4*)g_q)[idx] = aq;
    ((float4*)g_k)[idx] = ak;
    ((float4*)g_v)[idx] = av;
}

// ---------------------------------------------------------------------------
// Kernel 2: windowed softmax attention, 2 adjacent outputs/thread.
// Grid = 896 blocks, one wave (<=148x8 resident); each block runs 2 tiles
// that share (ht, c) and differ only in batch (b, b+2) -> rel/bias hoisted.
// ---------------------------------------------------------------------------
__global__ __launch_bounds__(224, 8)
void attn_kernel(const float* __restrict__ rel_x,
                 const float* __restrict__ rel_y,
                 const float* __restrict__ bk,
                 const float* __restrict__ bv,
                 float* __restrict__ out) {
    __shared__ __align__(16) float ks_[TRW*SP];
    __shared__ __align__(16) float vs_[TRW*SP];

    int t  = blockIdx.x;        // 0..895
    int ht = t % 7;             // row tile (shared by both batches)
    int cb = t / 7;
    int c  = cb & 63;
    int b0 = cb >> 6;           // 0 or 1; second tile uses b0+2
    int h0 = ht * TH;
    int tid = threadIdx.x;
    int d = c & 7;

    float kb = __ldg(&bk[c]);
    float vb = __ldg(&bv[c]);

    float relv[7];
    #pragma unroll
    for (int jj = 0; jj < 7; jj++)
        relv[jj] = (d < 4) ? __ldg(&rel_x[d*KS + jj]) : __ldg(&rel_y[(d-4)*KS + jj]);

    int r  = tid / 28;          // local row 0..7
    int wp = tid - r*28;        // col pair 0..27
    int h  = h0 + r;
    int w0 = wp * 2;

    for (int bb = b0; bb < B; bb += 2) {
        int cbase = (bb*COUT + c)*H;

        if (bb != b0) __syncthreads();   // protect smem reuse across tiles

        // stage padded 14x62 tile; halo = bias
        for (int i = tid; i < TRW*64; i += 224) {
            int pr = i >> 6, pc = i & 63;
            int hy = h0 + pr - PAD, wx = pc - PAD;
            bool in = ((unsigned)hy < (unsigned)H) && ((unsigned)wx < (unsigned)W);
            int gi = (cbase + hy)*W + wx;
            int si = pr*SP + pc;
            ks_[si] = in ? g_k[gi] : kb;
            vs_[si] = in ? g_v[gi] : vb;
        }
        __syncthreads();

        float2 qv = ((const float2*)g_q)[(cbase + h)*28 + wp];  // pre-scaled by log2e
        float q0 = qv.x, q1 = qv.y;

        float s0 = 0.f, s1 = 0.f, o0 = 0.f, o1 = 0.f;

        if (d < 4) {
            #pragma unroll
            for (int jy = 0; jy < KS; jy++) {
                const float2* kp = (const float2*)(ks_ + (r + jy)*SP + w0);
                const float2* vp = (const float2*)(vs_ + (r + jy)*SP + w0);
                float2 ka = kp[0], kc = kp[1], ke = kp[2], kg = kp[3];
                float2 va = vp[0], vc = vp[1], ve = vp[2], vg = vp[3];
                float a0 = q0 * relv[jy];
                float a1 = q1 * relv[jy];
                float e;
                EX2F(e, fmaf(q0, ka.x, a0)); s0 += e; o0 = fmaf(e, va.x, o0);
                EX2F(e, fmaf(q0, ka.y, a0)); s0 += e; o0 = fmaf(e, va.y, o0);
                EX2F(e, fmaf(q0, kc.x, a0)); s0 += e; o0 = fmaf(e, vc.x, o0);
                EX2F(e, fmaf(q0, kc.y, a0)); s0 += e; o0 = fmaf(e, vc.y, o0);
                EX2F(e, fmaf(q0, ke.x, a0)); s0 += e; o0 = fmaf(e, ve.x, o0);
                EX2F(e, fmaf(q0, ke.y, a0)); s0 += e; o0 = fmaf(e, ve.y, o0);
                EX2F(e, fmaf(q0, kg.x, a0)); s0 += e; o0 = fmaf(e, vg.x, o0);
                EX2F(e, fmaf(q1, ka.y, a1)); s1 += e; o1 = fmaf(e, va.y, o1);
                EX2F(e, fmaf(q1, kc.x, a1)); s1 += e; o1 = fmaf(e, vc.x, o1);
                EX2F(e, fmaf(q1, kc.y, a1)); s1 += e; o1 = fmaf(e, vc.y, o1);
                EX2F(e, fmaf(q1, ke.x, a1)); s1 += e; o1 = fmaf(e, ve.x, o1);
                EX2F(e, fmaf(q1, ke.y, a1)); s1 += e; o1 = fmaf(e, ve.y, o1);
                EX2F(e, fmaf(q1, kg.x, a1)); s1 += e; o1 = fmaf(e, vg.x, o1);
                EX2F(e, fmaf(q1, kg.y, a1)); s1 += e; o1 = fmaf(e, vg.y, o1);
            }
        } else {
            #pragma unroll
            for (int jy = 0; jy < KS; jy++) {
                const float2* kp = (const float2*)(ks_ + (r + jy)*SP + w0);
                const float2* vp = (const float2*)(vs_ + (r + jy)*SP + w0);
                float2 ka = kp[0], kc = kp[1], ke = kp[2], kg = kp[3];
                float2 va = vp[0], vc = vp[1], ve = vp[2], vg = vp[3];
                float e;
                EX2F(e, fmaf(q0, ka.x, q0*relv[0])); s0 += e; o0 = fmaf(e, va.x, o0);
                EX2F(e, fmaf(q0, ka.y, q0*relv[1])); s0 += e; o0 = fmaf(e, va.y, o0);
                EX2F(e, fmaf(q0, kc.x, q0*relv[2])); s0 += e; o0 = fmaf(e, vc.x, o0);
                EX2F(e, fmaf(q0, kc.y, q0*relv[3])); s0 += e; o0 = fmaf(e, vc.y, o0);
                EX2F(e, fmaf(q0, ke.x, q0*relv[4])); s0 += e; o0 = fmaf(e, ve.x, o0);
                EX2F(e, fmaf(q0, ke.y, q0*relv[5])); s0 += e; o0 = fmaf(e, ve.y, o0);
                EX2F(e, fmaf(q0, kg.x, q0*relv[6])); s0 += e; o0 = fmaf(e, vg.x, o0);
                EX2F(e, fmaf(q1, ka.y, q1*relv[0])); s1 += e; o1 = fmaf(e, va.y, o1);
                EX2F(e, fmaf(q1, kc.x, q1*relv[1])); s1 += e; o1 = fmaf(e, vc.x, o1);
                EX2F(e, fmaf(q1, kc.y, q1*relv[2])); s1 += e; o1 = fmaf(e, vc.y, o1);
                EX2F(e, fmaf(q1, ke.x, q1*relv[3])); s1 += e; o1 = fmaf(e, ve.x, o1);
                EX2F(e, fmaf(q1, ke.y, q1*relv[4])); s1 += e; o1 = fmaf(e, ve.y, o1);
                EX2F(e, fmaf(q1, kg.x, q1*relv[5])); s1 += e; o1 = fmaf(e, vg.x, o1);
                EX2F(e, fmaf(q1, kg.y, q1*relv[6])); s1 += e; o1 = fmaf(e, vg.y, o1);
            }
        }

        float2 res;
        res.x = __fdividef(o0, s0);
        res.y = __fdividef(o1, s1);
        *(float2*)&out[(cbase + h)*W + w0] = res;
    }
}

// ---------------------------------------------------------------------------
extern "C" void kernel_launch(void* const* d_in, const int* in_sizes, int n_in,
                              void* d_out, int out_size) {
    const float* x     = (const float*)d_in[0];
    const float* wq    = (const float*)d_in[1];
    const float* wk    = (const float*)d_in[2];
    const float* bk    = (const float*)d_in[3];
    const float* wv    = (const float*)d_in[4];
    const float* bv    = (const float*)d_in[5];
    const float* rel_x = (const float*)d_in[6];
    const float* rel_y = (const float*)d_in[7];
    float* out = (float*)d_out;

    qkv_kernel<<<784, 256>>>(x, wq, wk, bk, wv, bv);

    attn_kernel<<<896, 224>>>(rel_x, rel_y, bk, bv, out);  // single wave, 2 tiles/block
}

// round 7
// speedup vs baseline: 1.1067x; 1.1067x over previous
#include <cuda_runtime.h>

#define G     8
#define CIN   64
#define COUT  64
#define KS    7
#define PAD   3
#define H     56
#define W     56
#define B     4

#define TH    8             // output rows per attn tile
#define TRW   (TH + KS - 1) // 14 staged rows
#define SP    66            // shared row stride (floats), even + bank stagger

// scratch (allocation-free rule), interior 56x56 layout
__device__ float g_q[B*COUT*H*W];
__device__ float g_k[B*COUT*H*W];
__device__ float g_v[B*COUT*H*W];

#define EX2F(dst, src) asm("ex2.approx.ftz.f32 %0, %1;" : "=f"(dst) : "f"(src))

// ---------------------------------------------------------------------------
// Kernel 1: fused grouped 1x1 conv, 4 outputs/thread (float4).
// log2(e) folded into wq.
// ---------------------------------------------------------------------------
__global__ __launch_bounds__(256)
void qkv_kernel(const float* __restrict__ x,
                const float* __restrict__ wq,
                const float* __restrict__ wk,
                const float* __restrict__ bk,
                const float* __restrict__ wv,
                const float* __restrict__ bv) {
    const float LOG2E = 1.4426950408889634f;
    int idx = blockIdx.x * 256 + threadIdx.x;          // 200,704 threads exact
    int t = idx / 14;
    int j = idx - t*14;
    int h = t % 56;  t /= 56;
    int c = t % 64;
    int b = t / 64;
    int g = c >> 3;

    const float4* xp = (const float4*)x + ((b*CIN + g*8)*H + h)*14 + j;

    float kb = __ldg(&bk[c]);
    float vb = __ldg(&bv[c]);
    float4 aq = make_float4(0.f, 0.f, 0.f, 0.f);
    float4 ak = make_float4(kb, kb, kb, kb);
    float4 av = make_float4(vb, vb, vb, vb);

    #pragma unroll
    for (int i = 0; i < 8; i++) {
        float4 xv  = __ldg(xp + i*784);                 // 784 = H*W/4
        float wqi  = __ldg(&wq[c*8 + i]) * LOG2E;
        float wki  = __ldg(&wk[c*8 + i]);
        float wvi  = __ldg(&wv[c*8 + i]);
        aq.x = fmaf(wqi, xv.x, aq.x); aq.y = fmaf(wqi, xv.y, aq.y);
        aq.z = fmaf(wqi, xv.z, aq.z); aq.w = fmaf(wqi, xv.w, aq.w);
        ak.x = fmaf(wki, xv.x, ak.x); ak.y = fmaf(wki, xv.y, ak.y);
        ak.z = fmaf(wki, xv.z, ak.z); ak.w = fmaf(wki, xv.w, ak.w);
        av.x = fmaf(wvi, xv.x, av.x); av.y = fmaf(wvi, xv.y, av.y);
        av.z = fmaf(wvi, xv.z, av.z); av.w = fmaf(wvi, xv.w, av.w);
    }
    ((float4*)g_q)[idx] = aq;
    ((float4*)g_k)[idx] = ak;
    ((float4*)g_v)[idx] = av;
}

// ---------------------------------------------------------------------------
// Kernel 2: windowed softmax attention, 2 adjacent outputs/thread.
// Grid 1792, 224 thr. launch_bounds(224,6): allow up to 48 regs so ptxas can
// keep many EX2 results + next-row k/v in flight (ILP > occupancy here; wave
// conservation caps avg warps/SM at ~42 regardless).
// Split accumulators halve the FADD/FFMA dependency chains.
// ---------------------------------------------------------------------------
__global__ __launch_bounds__(224, 6)
void attn_kernel(const float* __restrict__ rel_x,
                 const float* __restrict__ rel_y,
                 const float* __restrict__ bk,
                 const float* __restrict__ bv,
                 float* __restrict__ out) {
    __shared__ __align__(16) float ks_[TRW*SP];
    __shared__ __align__(16) float vs_[TRW*SP];

    int ht = blockIdx.x;   // 0..6
    int c  = blockIdx.y;   // 0..63
    int b  = blockIdx.z;   // 0..3
    int h0 = ht * TH;
    int tid = threadIdx.x;
    int d = c & 7;

    int r  = tid / 28;          // local row 0..7
    int wp = tid - r*28;        // col pair 0..27
    int h  = h0 + r;
    int w0 = wp * 2;
    int cbase = (b*COUT + c)*H;

    // prefetch per-thread state BEFORE staging (overlap L2 latency)
    float2 qv = ((const float2*)g_q)[(cbase + h)*28 + wp];  // pre-scaled by log2e
    float relv[7];
    #pragma unroll
    for (int jj = 0; jj < 7; jj++)
        relv[jj] = (d < 4) ? __ldg(&rel_x[d*KS + jj]) : __ldg(&rel_y[(d-4)*KS + jj]);
    float kb = __ldg(&bk[c]);
    float vb = __ldg(&bv[c]);

    // stage padded 14x62 tile; halo = bias
    for (int i = tid; i < TRW*64; i += 224) {
        int pr = i >> 6, pc = i & 63;
        int hy = h0 + pr - PAD, wx = pc - PAD;
        bool in = ((unsigned)hy < (unsigned)H) && ((unsigned)wx < (unsigned)W);
        int gi = (cbase + hy)*W + wx;
        int si = pr*SP + pc;
        ks_[si] = in ? g_k[gi] : kb;
        vs_[si] = in ? g_v[gi] : vb;
    }
    __syncthreads();

    float q0 = qv.x, q1 = qv.y;

    // split accumulators: two independent chains per output
    float s0a = 0.f, s0b = 0.f, s1a = 0.f, s1b = 0.f;
    float o0a = 0.f, o0b = 0.f, o1a = 0.f, o1b = 0.f;

    if (d < 4) {
        #pragma unroll
        for (int jy = 0; jy < KS; jy++) {
            const float2* kp = (const float2*)(ks_ + (r + jy)*SP + w0);
            const float2* vp = (const float2*)(vs_ + (r + jy)*SP + w0);
            float2 ka = kp[0], kc = kp[1], ke = kp[2], kg = kp[3];
            float2 va = vp[0], vc = vp[1], ve = vp[2], vg = vp[3];
            float a0 = q0 * relv[jy];
            float a1 = q1 * relv[jy];
            float e;
            EX2F(e, fmaf(q0, ka.x, a0)); s0a += e; o0a = fmaf(e, va.x, o0a);
            EX2F(e, fmaf(q0, ka.y, a0)); s0b += e; o0b = fmaf(e, va.y, o0b);
            EX2F(e, fmaf(q0, kc.x, a0)); s0a += e; o0a = fmaf(e, vc.x, o0a);
            EX2F(e, fmaf(q0, kc.y, a0)); s0b += e; o0b = fmaf(e, vc.y, o0b);
            EX2F(e, fmaf(q0, ke.x, a0)); s0a += e; o0a = fmaf(e, ve.x, o0a);
            EX2F(e, fmaf(q0, ke.y, a0)); s0b += e; o0b = fmaf(e, ve.y, o0b);
            EX2F(e, fmaf(q0, kg.x, a0)); s0a += e; o0a = fmaf(e, vg.x, o0a);
            EX2F(e, fmaf(q1, ka.y, a1)); s1a += e; o1a = fmaf(e, va.y, o1a);
            EX2F(e, fmaf(q1, kc.x, a1)); s1b += e; o1b = fmaf(e, vc.x, o1b);
            EX2F(e, fmaf(q1, kc.y, a1)); s1a += e; o1a = fmaf(e, vc.y, o1a);
            EX2F(e, fmaf(q1, ke.x, a1)); s1b += e; o1b = fmaf(e, ve.x, o1b);
            EX2F(e, fmaf(q1, ke.y, a1)); s1a += e; o1a = fmaf(e, ve.y, o1a);
            EX2F(e, fmaf(q1, kg.x, a1)); s1b += e; o1b = fmaf(e, vg.x, o1b);
            EX2F(e, fmaf(q1, kg.y, a1)); s1a += e; o1a = fmaf(e, vg.y, o1a);
        }
    } else {
        #pragma unroll
        for (int jy = 0; jy < KS; jy++) {
            const float2* kp = (const float2*)(ks_ + (r + jy)*SP + w0);
            const float2* vp = (const float2*)(vs_ + (r + jy)*SP + w0);
            float2 ka = kp[0], kc = kp[1], ke = kp[2], kg = kp[3];
            float2 va = vp[0], vc = vp[1], ve = vp[2], vg = vp[3];
            float e;
            EX2F(e, fmaf(q0, ka.x, q0*relv[0])); s0a += e; o0a = fmaf(e, va.x, o0a);
            EX2F(e, fmaf(q0, ka.y, q0*relv[1])); s0b += e; o0b = fmaf(e, va.y, o0b);
            EX2F(e, fmaf(q0, kc.x, q0*relv[2])); s0a += e; o0a = fmaf(e, vc.x, o0a);
            EX2F(e, fmaf(q0, kc.y, q0*relv[3])); s0b += e; o0b = fmaf(e, vc.y, o0b);
            EX2F(e, fmaf(q0, ke.x, q0*relv[4])); s0a += e; o0a = fmaf(e, ve.x, o0a);
            EX2F(e, fmaf(q0, ke.y, q0*relv[5])); s0b += e; o0b = fmaf(e, ve.y, o0b);
            EX2F(e, fmaf(q0, kg.x, q0*relv[6])); s0a += e; o0a = fmaf(e, vg.x, o0a);
            EX2F(e, fmaf(q1, ka.y, q1*relv[0])); s1a += e; o1a = fmaf(e, va.y, o1a);
            EX2F(e, fmaf(q1, kc.x, q1*relv[1])); s1b += e; o1b = fmaf(e, vc.x, o1b);
            EX2F(e, fmaf(q1, kc.y, q1*relv[2])); s1a += e; o1a = fmaf(e, vc.y, o1a);
            EX2F(e, fmaf(q1, ke.x, q1*relv[3])); s1b += e; o1b = fmaf(e, ve.x, o1b);
            EX2F(e, fmaf(q1, ke.y, q1*relv[4])); s1a += e; o1a = fmaf(e, ve.y, o1a);
            EX2F(e, fmaf(q1, kg.x, q1*relv[5])); s1b += e; o1b = fmaf(e, vg.x, o1b);
            EX2F(e, fmaf(q1, kg.y, q1*relv[6])); s1a += e; o1a = fmaf(e, vg.y, o1a);
        }
    }

    float2 res;
    res.x = __fdividef(o0a + o0b, s0a + s0b);
    res.y = __fdividef(o1a + o1b, s1a + s1b);
    *(float2*)&out[(cbase + h)*W + w0] = res;
}

// ---------------------------------------------------------------------------
extern "C" void kernel_launch(void* const* d_in, const int* in_sizes, int n_in,
                              void* d_out, int out_size) {
    const float* x     = (const float*)d_in[0];
    const float* wq    = (const float*)d_in[1];
    const float* wk    = (const float*)d_in[2];
    const float* bk    = (const float*)d_in[3];
    const float* wv    = (const float*)d_in[4];
    const float* bv    = (const float*)d_in[5];
    const float* rel_x = (const float*)d_in[6];
    const float* rel_y = (const float*)d_in[7];
    float* out = (float*)d_out;

    qkv_kernel<<<784, 256>>>(x, wq, wk, bk, wv, bv);

    dim3 grid(H/TH, COUT, B);   // (7, 64, 4) = 1792 blocks
    attn_kernel<<<grid, 224>>>(rel_x, rel_y, bk, bv, out);
}